// round 6
// baseline (speedup 1.0000x reference)
#include <cuda_runtime.h>
#include <cuda_fp16.h>
#include <cstdint>

// ============================================================================
// HelixMemory, fused single-pass design:
//   out[b, 0:254]      = cm[r]   = memory[2r+2] @ F0 + memory[2r+3] @ F1
//   out[b, 254:510]    = cx[b,t] = x[b,2t] @ F0 + x[b,2t+1] @ F1
//   out[b, 510:2046]   = memory[1022:2558]
//   out[b, 2046:2558]  = x[b]
// kernel 1: conv_filters  -> g_Bt[n][k] fp16 (4 MB)
// kernel 2: mega          -> heterogeneous grid:
//   - 528 GEMM CTAs: fp16 mma.sync m16n8k16, A read fp32 via cp.async and
//     converted to fp16 during fragment load; cm tiles (bm>=64) broadcast
//     results to all 32 batches directly in the epilogue.
//   - 264 copy CTAs (interleaved, blk%3==2): x passthrough + memory-tail
//     broadcast, streaming on the DRAM pipe while GEMM CTAs use tensor.
// ============================================================================

namespace {
constexpr int D_       = 1024;
constexpr int KDIM     = 2048;
constexpr int OUT_ROWS = 2558;
constexpr int CM_ROWS  = 254;
constexpr int BATCH    = 32;
constexpr int SEQ      = 512;

constexpr int BM = 128, BN = 128, BK = 64;       // BK in elements (k)
constexpr int KT = KDIM / BK;                    // 32

constexpr int PITCH_AF = 72;                     // A pitch, fp32 elements
constexpr int PITCH_BH = 72;                     // B pitch, fp16 elements
constexpr int PITCH_BU = PITCH_BH / 2;           // 36 uint32
constexpr int A_TILE_B = BM * PITCH_AF * 4;      // 36864 B
constexpr int B_TILE_B = BM * PITCH_BH * 2;      // 18432 B
constexpr int STAGE_B  = A_TILE_B + B_TILE_B;    // 55296 B
constexpr int SMEM_BYTES = 2 * STAGE_B;          // 110592 B (2 stages, occ 2)

constexpr int GEMM_BLOCKS = 8 * 66;              // 528
constexpr int COPY_BLOCKS = GEMM_BLOCKS / 2;     // 264
constexpr int PASS_BLOCKS = 150;                 // passthrough share
constexpr int BCST_BLOCKS = COPY_BLOCKS - PASS_BLOCKS;  // 114
constexpr int TOTAL_BLOCKS = GEMM_BLOCKS + COPY_BLOCKS; // 792
}

__device__ __align__(128) __half g_Bt[D_ * KDIM];   // 4 MB, filters^T [n][k]

// ---------------------------------------------------------------------------
__device__ __forceinline__ uint32_t smem_u32(const void* p) {
    uint32_t a;
    asm("{ .reg .u64 t; cvta.to.shared.u64 t, %1; cvt.u32.u64 %0, t; }" : "=r"(a) : "l"(p));
    return a;
}
__device__ __forceinline__ void cp16(uint32_t s, const void* g) {
    asm volatile("cp.async.cg.shared.global [%0], [%1], 16;" :: "r"(s), "l"(g));
}
__device__ __forceinline__ void mma_f16(float* c, const uint32_t* a, const uint32_t* b) {
    asm volatile(
        "mma.sync.aligned.m16n8k16.row.col.f32.f16.f16.f32 "
        "{%0,%1,%2,%3}, {%4,%5,%6,%7}, {%8,%9}, {%0,%1,%2,%3};"
        : "+f"(c[0]), "+f"(c[1]), "+f"(c[2]), "+f"(c[3])
        : "r"(a[0]), "r"(a[1]), "r"(a[2]), "r"(a[3]), "r"(b[0]), "r"(b[1]));
}
__device__ __forceinline__ uint32_t pack_h2(float x, float y) {
    __half2 h = __floats2half2_rn(x, y);
    return *reinterpret_cast<uint32_t*>(&h);
}

// ---------------------------------------------------------------------------
// g_Bt[n][k] = fp16(F[k][n])
// ---------------------------------------------------------------------------
__global__ __launch_bounds__(256) void conv_filters(const float* __restrict__ F)
{
    __shared__ float tile[64][33];
    const int n0 = blockIdx.x * 32;
    const int k0 = blockIdx.y * 64;
    const int tx = threadIdx.x, ty = threadIdx.y;      // 32 x 8
    #pragma unroll
    for (int i = ty; i < 64; i += 8)
        tile[i][tx] = F[(size_t)(k0 + i) * D_ + n0 + tx];
    __syncthreads();
    uint32_t* bt = reinterpret_cast<uint32_t*>(g_Bt);
    #pragma unroll
    for (int i = ty; i < 32; i += 8)
        bt[(size_t)(n0 + i) * (KDIM / 2) + k0 / 2 + tx] =
            pack_h2(tile[2 * tx][i], tile[2 * tx + 1][i]);
}

// ---------------------------------------------------------------------------
// copy CTA body
// ---------------------------------------------------------------------------
__device__ __forceinline__ void copy_body(
    int cid, const float* __restrict__ inputs, const float* __restrict__ memory,
    float* __restrict__ out)
{
    const int tid = threadIdx.x;
    if (cid < PASS_BLOCKS) {
        // out[b, 2046:2558] = inputs[b]
        constexpr int PER_B  = SEQ * D_ / 4;                  // 131072 f4
        constexpr int TOTAL  = BATCH * PER_B;                 // 4,194,304
        const int stride = PASS_BLOCKS * 256;
        const float4* in4 = reinterpret_cast<const float4*>(inputs);
        float4*      out4 = reinterpret_cast<float4*>(out);
        for (int idx = cid * 256 + tid; idx < TOTAL; idx += stride) {
            const int b = idx / PER_B, rem = idx - b * PER_B;
            out4[(size_t)b * (OUT_ROWS * D_ / 4) + 2046 * (D_ / 4) + rem] = in4[idx];
        }
    } else {
        // out[b, 510:2046] = memory[1022:2558]
        constexpr int PER_B = 1536 * D_ / 4;                  // 393216 f4
        constexpr int TOTAL = BATCH * PER_B;
        const int c = cid - PASS_BLOCKS;
        const int stride = BCST_BLOCKS * 256;
        const float4* mem4 = reinterpret_cast<const float4*>(memory) + 1022 * (D_ / 4);
        float4* out4 = reinterpret_cast<float4*>(out);
        for (int idx = c * 256 + tid; idx < TOTAL; idx += stride) {
            const int b = idx / PER_B, rem = idx - b * PER_B;
            out4[(size_t)b * (OUT_ROWS * D_ / 4) + 510 * (D_ / 4) + rem] = mem4[rem];
        }
    }
}

// ---------------------------------------------------------------------------
// mega kernel: heterogeneous grid (GEMM tiles + copy CTAs interleaved)
// ---------------------------------------------------------------------------
__global__ __launch_bounds__(256, 2) void mega(
    const float* __restrict__ A_in, const float* __restrict__ A_mem,
    const float* __restrict__ inputs, const float* __restrict__ memory,
    float* __restrict__ out)
{
    const int blk = blockIdx.x;
    if (blk % 3 == 2) {                       // copy CTA
        copy_body(blk / 3, inputs, memory, out);
        return;
    }
    const int gid = (blk / 3) * 2 + (blk % 3);  // 0..527
    const int bm  = gid >> 3;
    const int bn  = gid & 7;
    const int n0  = bn * BN;

    extern __shared__ char smem[];
    const uint32_t sbase = smem_u32(smem);

    const int tid  = threadIdx.x;
    const int wid  = tid >> 5;
    const int lane = tid & 31;
    const int g    = lane >> 2;
    const int t    = lane & 3;
    const int wm   = wid & 3;             // 4 warps x 32 rows
    const int wn   = wid >> 2;            // 2 warps x 64 cols

    const float* Abase = (bm < 64) ? (A_in + (size_t)bm * BM * KDIM)
                                   : (A_mem + (size_t)(bm - 64) * BM * KDIM);

    auto issue = [&](int kt) {
        const int s = kt & 1;
        const uint32_t sA = sbase + (uint32_t)s * STAGE_B;
        const uint32_t sB = sA + (uint32_t)A_TILE_B;
        const int k0 = kt * BK;
        #pragma unroll
        for (int i = 0; i < 8; ++i) {     // A: 128 rows x 64 f32 = 2048 chunks
            const int q   = tid + 256 * i;
            const int row = q >> 4;
            const int c   = q & 15;
            cp16(sA + (uint32_t)(row * PITCH_AF + c * 4) * 4,
                 Abase + (size_t)row * KDIM + k0 + c * 4);
        }
        #pragma unroll
        for (int i = 0; i < 4; ++i) {     // B: 128 rows x 64 f16 = 1024 chunks
            const int q   = tid + 256 * i;
            const int row = q >> 3;
            const int c   = q & 7;
            cp16(sB + (uint32_t)(row * PITCH_BH + c * 8) * 2,
                 g_Bt + (size_t)(n0 + row) * KDIM + k0 + c * 8);
        }
        asm volatile("cp.async.commit_group;" ::: "memory");
    };

    float c[2][8][4] = {};

    issue(0);

    for (int kt = 0; kt < KT; ++kt) {
        if (kt + 1 < KT) {
            issue(kt + 1);
            asm volatile("cp.async.wait_group 1;" ::: "memory");
        } else {
            asm volatile("cp.async.wait_group 0;" ::: "memory");
        }
        __syncthreads();

        const int s = kt & 1;
        const float*    As = reinterpret_cast<const float*>(smem + s * STAGE_B);
        const uint32_t* Bs = reinterpret_cast<const uint32_t*>(smem + s * STAGE_B + A_TILE_B);

        #pragma unroll
        for (int ks = 0; ks < 4; ++ks) {           // 4 x k16 = BK 64
            uint32_t a[2][4];
            #pragma unroll
            for (int mt = 0; mt < 2; ++mt) {
                const float* ap = As + (wm * 32 + mt * 16 + g) * PITCH_AF + ks * 16 + 2 * t;
                float2 v0 = *reinterpret_cast<const float2*>(ap);
                float2 v1 = *reinterpret_cast<const float2*>(ap + 8 * PITCH_AF);
                float2 v2 = *reinterpret_cast<const float2*>(ap + 8);
                float2 v3 = *reinterpret_cast<const float2*>(ap + 8 * PITCH_AF + 8);
                a[mt][0] = pack_h2(v0.x, v0.y);
                a[mt][1] = pack_h2(v1.x, v1.y);
                a[mt][2] = pack_h2(v2.x, v2.y);
                a[mt][3] = pack_h2(v3.x, v3.y);
            }
            uint32_t bf[8][2];
            #pragma unroll
            for (int nt = 0; nt < 8; ++nt) {
                const uint32_t* bp = Bs + (wn * 64 + nt * 8 + g) * PITCH_BU + ks * 8 + t;
                bf[nt][0] = bp[0];
                bf[nt][1] = bp[4];
            }
            #pragma unroll
            for (int mt = 0; mt < 2; ++mt)
                #pragma unroll
                for (int nt = 0; nt < 8; ++nt)
                    mma_f16(c[mt][nt], a[mt], bf[nt]);
        }
        __syncthreads();
    }

    // ---- epilogue ----------------------------------------------------------
    #pragma unroll
    for (int mt = 0; mt < 2; ++mt) {
        #pragma unroll
        for (int half = 0; half < 2; ++half) {
            const int rloc = wm * 32 + mt * 16 + half * 8 + g;
            if (bm < 64) {
                // compress(x): one batch-specific row
                const int r = bm * BM + rloc;
                const int b = r >> 8, tt = r & 255;
                float* dst = out + ((size_t)b * OUT_ROWS + 254 + tt) * D_ + n0 + wn * 64;
                #pragma unroll
                for (int nt = 0; nt < 8; ++nt) {
                    float2 v = make_float2(c[mt][nt][half * 2], c[mt][nt][half * 2 + 1]);
                    *reinterpret_cast<float2*>(dst + nt * 8 + t * 2) = v;
                }
            } else {
                // compressed-memory row: broadcast to all 32 batches
                const int r = (bm - 64) * BM + rloc;
                if (r < CM_ROWS) {
                    float* dst0 = out + (size_t)r * D_ + n0 + wn * 64;
                    #pragma unroll
                    for (int nt = 0; nt < 8; ++nt) {
                        float2 v = make_float2(c[mt][nt][half * 2], c[mt][nt][half * 2 + 1]);
                        float* dp = dst0 + nt * 8 + t * 2;
                        for (int b = 0; b < BATCH; ++b)
                            *reinterpret_cast<float2*>(dp + (size_t)b * OUT_ROWS * D_) = v;
                    }
                }
            }
        }
    }
}

// ---------------------------------------------------------------------------
extern "C" void kernel_launch(void* const* d_in, const int* in_sizes, int n_in,
                              void* d_out, int out_size)
{
    const float* inputs  = (const float*)d_in[0];  // (32, 512, 1024)
    const float* memory  = (const float*)d_in[1];  // (2558, 1024)
    const float* filters = (const float*)d_in[2];  // (2, 1024, 1024)
    float* out = (float*)d_out;                    // (32, 2558, 1024)

    cudaFuncSetAttribute(mega, cudaFuncAttributeMaxDynamicSharedMemorySize,
                         SMEM_BYTES);

    // 1) B^T fp16
    conv_filters<<<dim3(D_ / 32, KDIM / 64), dim3(32, 8)>>>(filters);
    // 2) fused GEMM + copy
    mega<<<TOTAL_BLOCKS, 256, SMEM_BYTES>>>(
        inputs, memory + 2 * D_, inputs, memory, out);
}